// round 3
// baseline (speedup 1.0000x reference)
#include <cuda_runtime.h>
#include <cuda_fp16.h>

// Problem constants (fixed by the benchmark)
constexpr int kB = 2;
constexpr int kM = 4096;
constexpr int kC = 256;
constexpr int kH = 64;
constexpr int kW = 64;
constexpr int kLevels = 4;
constexpr int kRad = 4;
constexpr int kSide = 9;                 // 2*kRad+1
constexpr int kFeat = kLevels * kSide * kSide;  // 324
constexpr int kPyrStride = 4096 + 1024 + 256 + 64;  // 5440 positions per batch

// Static device scratch (no runtime allocation allowed)
__device__ float  g_pyrf[(size_t)kB * kPyrStride * kC];   // fp32 pooling chain
__device__ __half g_pyrh[(size_t)kB * kPyrStride * kC];   // fp16 read path

__constant__ int c_lvl_off[4] = {0, 4096, 5120, 5376};

// ---------------------------------------------------------------------------
// Kernel 1: transpose fmap2 (B,C,H,W) -> (B, y*W+x, C), write fp32 + fp16
// Block: 32x32. Grid: B * H * (W/32) * (C/32) = 2*64*2*8 = 2048
// ---------------------------------------------------------------------------
__global__ void k_transpose(const float* __restrict__ fmap2) {
    __shared__ float s[32][33];
    int bidx = blockIdx.x;
    int ct = bidx & 7;  bidx >>= 3;   // channel tile (8)
    int xt = bidx & 1;  bidx >>= 1;   // x tile (2)
    int y  = bidx & 63; bidx >>= 6;   // row (64)
    int b  = bidx;                    // batch (2)

    int tx = threadIdx.x, ty = threadIdx.y;
    int cc = ct * 32 + ty;
    int xx = xt * 32 + tx;
    // coalesced read along x for channel cc
    s[ty][tx] = fmap2[(((size_t)b * kC + cc) * kH + y) * kW + xx];
    __syncthreads();
    // write: position (y, xt*32+ty), channel ct*32+tx  -> coalesced along C
    float v = s[tx][ty];
    size_t o = ((size_t)b * kPyrStride + (size_t)y * kW + (xt * 32 + ty)) * kC + (ct * 32 + tx);
    g_pyrf[o] = v;
    g_pyrh[o] = __float2half(v);
}

// ---------------------------------------------------------------------------
// Kernel 2: 2x2 average pool level (lvl-1) -> lvl in the transposed layout
// ---------------------------------------------------------------------------
__global__ void k_pool(int lvl, int n) {
    int idx = blockIdx.x * blockDim.x + threadIdx.x;
    if (idx >= n) return;
    int Wl = kW >> lvl;
    int Hl = kH >> lvl;
    int c   = idx & (kC - 1);
    int pos = idx >> 8;
    int x = pos % Wl; pos /= Wl;
    int y = pos % Hl;
    int b = pos / Hl;
    int Wp = Wl * 2;

    size_t inb = ((size_t)b * kPyrStride + c_lvl_off[lvl - 1] + (size_t)(2 * y) * Wp + 2 * x) * kC + c;
    float v = 0.25f * (g_pyrf[inb] + g_pyrf[inb + kC] +
                       g_pyrf[inb + (size_t)Wp * kC] + g_pyrf[inb + (size_t)Wp * kC + kC]);
    size_t o = ((size_t)b * kPyrStride + c_lvl_off[lvl] + (size_t)y * Wl + x) * kC + c;
    g_pyrf[o] = v;
    g_pyrh[o] = __float2half(v);
}

// ---------------------------------------------------------------------------
// Kernel 3: one block (256 thr, 8 warps) per query.
// Per level: 100 taps (10x10 shared integer grid). Warp computes a tap's
// 256-dim dot: lane holds 8 channels (one 16B fp16 load), shuffle-reduce.
// Then 81 threads do the shared-weight bilinear combine and store.
// ---------------------------------------------------------------------------
__global__ __launch_bounds__(256) void k_sample(const float* __restrict__ fmap1,
                                                const float* __restrict__ coords,
                                                float* __restrict__ out) {
    int q = blockIdx.x;            // 0 .. B*M-1
    int b = q >> 12;               // / kM
    int m = q & (kM - 1);
    int tid  = threadIdx.x;
    int lane = tid & 31;
    int wid  = tid >> 5;

    __shared__ float Dsh[100];

    // f1 slice for this lane: 8 channels, loaded once, reused for all taps/levels
    const float4* f4 = reinterpret_cast<const float4*>(fmap1) + (size_t)q * (kC / 4) + lane * 2;
    float4 fA = f4[0];
    float4 fB = f4[1];

    float clx = coords[(size_t)q * 2 + 0];
    float cly = coords[(size_t)q * 2 + 1];

    for (int l = 0; l < kLevels; l++) {
        int Wl = kW >> l;
        int Hl = kH >> l;
        float fx0 = floorf(clx), fy0 = floorf(cly);
        int ix0 = (int)fx0 - kRad;
        int iy0 = (int)fy0 - kRad;
        float wx1 = clx - fx0, wx0 = 1.0f - wx1;
        float wy1 = cly - fy0, wy0 = 1.0f - wy1;
        size_t lbase = (size_t)b * kPyrStride + c_lvl_off[l];

        #pragma unroll 1
        for (int p = wid; p < 100; p += 8) {
            int py = p / 10;
            int px = p - py * 10;
            int txp = ix0 + px;
            int typ = iy0 + py;
            float part = 0.0f;
            if ((unsigned)txp < (unsigned)Wl && (unsigned)typ < (unsigned)Hl) {
                const __half* vp = &g_pyrh[(lbase + (size_t)typ * Wl + txp) * kC + lane * 8];
                uint4 u = *reinterpret_cast<const uint4*>(vp);
                const __half2* hp = reinterpret_cast<const __half2*>(&u);
                float2 p0 = __half22float2(hp[0]);
                float2 p1 = __half22float2(hp[1]);
                float2 p2 = __half22float2(hp[2]);
                float2 p3 = __half22float2(hp[3]);
                part  = p0.x * fA.x;
                part += p0.y * fA.y;
                part += p1.x * fA.z;
                part += p1.y * fA.w;
                part += p2.x * fB.x;
                part += p2.y * fB.y;
                part += p3.x * fB.z;
                part += p3.y * fB.w;
            }
            // warp reduce (valid is warp-uniform; zeros reduce to zero)
            #pragma unroll
            for (int s = 16; s; s >>= 1)
                part += __shfl_xor_sync(0xffffffffu, part, s);
            if (lane == 0) Dsh[p] = part;
        }
        __syncthreads();

        if (tid < 81) {
            int ixo = tid / 9;        // x-offset index (outer in reference)
            int iyo = tid - ixo * 9;  // y-offset index
            float d00 = Dsh[iyo * 10 + ixo];
            float d01 = Dsh[iyo * 10 + ixo + 1];
            float d10 = Dsh[iyo * 10 + ixo + 10];
            float d11 = Dsh[iyo * 10 + ixo + 11];
            float val = wy0 * (wx0 * d00 + wx1 * d01) + wy1 * (wx0 * d10 + wx1 * d11);
            out[((size_t)b * kFeat + l * 81 + tid) * kM + m] = val;
        }
        __syncthreads();

        clx *= 0.5f;
        cly *= 0.5f;
    }
}

// ---------------------------------------------------------------------------
extern "C" void kernel_launch(void* const* d_in, const int* in_sizes, int n_in,
                              void* d_out, int out_size) {
    const float* fmap1  = (const float*)d_in[0];
    const float* fmap2  = (const float*)d_in[1];
    const float* coords = (const float*)d_in[2];
    float* out = (float*)d_out;

    // Build the transposed fp32/fp16 pyramid of fmap2
    k_transpose<<<kB * kH * 2 * 8, dim3(32, 32)>>>(fmap2);
    for (int l = 1; l < kLevels; l++) {
        int Wl = kW >> l;
        int n = kB * Wl * Wl * kC;
        k_pool<<<(n + 255) / 256, 256>>>(l, n);
    }

    // One block per query
    k_sample<<<kB * kM, 256>>>(fmap1, coords, out);
}

// round 10
// speedup vs baseline: 1.4456x; 1.4456x over previous
#include <cuda_runtime.h>
#include <cuda_fp16.h>
#include <cstdint>

// ---------------------------------------------------------------------------
// Problem constants
// ---------------------------------------------------------------------------
constexpr int kB = 2;
constexpr int kM = 4096;
constexpr int kC = 256;
constexpr int kH = 64;
constexpr int kW = 64;
constexpr int kLevels = 4;
constexpr int kRad = 4;
constexpr int kSide = 9;
constexpr int kFeat = kLevels * kSide * kSide;          // 324
constexpr int kP    = 4096 + 1024 + 256 + 64;           // 5440 positions / batch
constexpr int kPPad = 5504;                             // 43 * 128
constexpr int kNT   = 43;                               // N tiles of 128
constexpr int kNSUB = 4;                                // N tiles per CTA
constexpr int kNGRP = 11;                               // ceil(43/4)

// Static device scratch (zero-initialized at load; padding rows stay zero)
__device__ float  g_pyrf[(size_t)kB * kPPad * kC];      // fp32 pooling chain
__device__ __half g_pyrh[(size_t)kB * kPPad * kC];      // fp16 GEMM B operand
__device__ __half g_f1h [(size_t)kB * kM * kC];         // fp16 GEMM A operand
__device__ float  g_corr[(size_t)kB * kM * kPPad];      // fp32 correlation pyramid

__constant__ int c_lvl_off[4] = {0, 4096, 5120, 5376};

// ---------------------------------------------------------------------------
// Helpers (baseline sm_90-era PTX only — NO 'a'-gated instructions)
// ---------------------------------------------------------------------------
__device__ __forceinline__ uint32_t smem_u32(const void* p) {
    uint32_t a;
    asm("{ .reg .u64 t; cvta.to.shared.u64 t, %1; cvt.u32.u64 %0, t; }" : "=r"(a) : "l"(p));
    return a;
}
__device__ __forceinline__ void cp16(uint32_t dst, const void* src) {
    asm volatile("cp.async.cg.shared.global [%0], [%1], 16;" :: "r"(dst), "l"(src));
}
__device__ __forceinline__ void cp_commit() {
    asm volatile("cp.async.commit_group;" ::: "memory");
}
__device__ __forceinline__ void cp_wait1() {
    asm volatile("cp.async.wait_group 1;" ::: "memory");
}
__device__ __forceinline__ void cp_wait0() {
    asm volatile("cp.async.wait_group 0;" ::: "memory");
}
__device__ __forceinline__ void mma16816(float* c, const uint32_t* a, const uint32_t* b) {
    asm volatile(
        "mma.sync.aligned.m16n8k16.row.col.f32.f16.f16.f32 "
        "{%0,%1,%2,%3}, {%4,%5,%6,%7}, {%8,%9}, {%0,%1,%2,%3};"
        : "+f"(c[0]), "+f"(c[1]), "+f"(c[2]), "+f"(c[3])
        : "r"(a[0]), "r"(a[1]), "r"(a[2]), "r"(a[3]), "r"(b[0]), "r"(b[1]));
}

// ---------------------------------------------------------------------------
// Kernel 1: transpose fmap2 (B,C,H,W) -> (B, pos, C), fp32 + fp16 (padded)
// ---------------------------------------------------------------------------
__global__ void k_transpose(const float* __restrict__ fmap2) {
    __shared__ float s[32][33];
    int bidx = blockIdx.x;
    int ct = bidx & 7;  bidx >>= 3;
    int xt = bidx & 1;  bidx >>= 1;
    int y  = bidx & 63; bidx >>= 6;
    int b  = bidx;
    int tx = threadIdx.x, ty = threadIdx.y;
    s[ty][tx] = fmap2[(((size_t)b * kC + ct * 32 + ty) * kH + y) * kW + (xt * 32 + tx)];
    __syncthreads();
    float v = s[tx][ty];
    size_t o = ((size_t)b * kPPad + (size_t)y * kW + (xt * 32 + ty)) * kC + (ct * 32 + tx);
    g_pyrf[o] = v;
    g_pyrh[o] = __float2half(v);
}

// ---------------------------------------------------------------------------
// Kernel 2: 2x2 average pool level lvl-1 -> lvl (transposed layout)
// ---------------------------------------------------------------------------
__global__ void k_pool(int lvl, int n) {
    int idx = blockIdx.x * blockDim.x + threadIdx.x;
    if (idx >= n) return;
    int Wl = kW >> lvl, Hl = kH >> lvl;
    int c = idx & (kC - 1);
    int pos = idx >> 8;
    int x = pos % Wl; pos /= Wl;
    int y = pos % Hl;
    int b = pos / Hl;
    int Wp = Wl * 2;
    size_t inb = ((size_t)b * kPPad + c_lvl_off[lvl - 1] + (size_t)(2 * y) * Wp + 2 * x) * kC + c;
    float v = 0.25f * (g_pyrf[inb] + g_pyrf[inb + kC] +
                       g_pyrf[inb + (size_t)Wp * kC] + g_pyrf[inb + (size_t)Wp * kC + kC]);
    size_t o = ((size_t)b * kPPad + c_lvl_off[lvl] + (size_t)y * Wl + x) * kC + c;
    g_pyrf[o] = v;
    g_pyrh[o] = __float2half(v);
}

// ---------------------------------------------------------------------------
// Kernel 3: fmap1 fp32 -> fp16
// ---------------------------------------------------------------------------
__global__ void k_f1cvt(const float4* __restrict__ f1) {
    int i = blockIdx.x * blockDim.x + threadIdx.x;
    float4 v = f1[i];
    __half2 a = __floats2half2_rn(v.x, v.y);
    __half2 b = __floats2half2_rn(v.z, v.w);
    uint2 u;
    u.x = *reinterpret_cast<uint32_t*>(&a);
    u.y = *reinterpret_cast<uint32_t*>(&b);
    reinterpret_cast<uint2*>(g_f1h)[i] = u;
}

// ---------------------------------------------------------------------------
// Kernel 4: HMMA GEMM  corr[b, m, p] = sum_c f1h[b,m,c] * pyrh[b,p,c]
// CTA: M=128 (full K=256 of A resident in smem), 4 N-subtiles of 128.
// B streamed in 64-k chunks, cp.async double-buffered, flattened pipeline.
// 8 warps in a 2(M) x 4(N) grid, warp tile 64x32, mma.sync m16n8k16.
// ---------------------------------------------------------------------------
constexpr int kAStrideH = 264;                 // 256 + 8 pad (halves)
constexpr int kABytes   = 128 * kAStrideH * 2; // 67584
constexpr int kBStrideH = 72;                  // 64 + 8 pad (halves)
constexpr int kBChunkBytes = 128 * kBStrideH * 2;  // 18432
constexpr int kGemmSmem = kABytes + 2 * kBChunkBytes;  // 104448

__device__ __forceinline__ void issueB(uint32_t sB, int tid, int b, int pbase, int kc) {
    const __half* src0 = g_pyrh + ((size_t)b * kPPad + pbase) * kC + kc * 64;
    #pragma unroll
    for (int j = 0; j < 4; j++) {
        int i = tid + j * 256;          // 1024 x 16B
        int n = i >> 3, seg = i & 7;
        cp16(sB + n * (kBStrideH * 2) + seg * 16, src0 + (size_t)n * kC + seg * 8);
    }
}

__global__ void __launch_bounds__(256) k_gemm() {
    extern __shared__ char smem[];
    char* smA = smem;
    uint32_t sAu = smem_u32(smA);
    uint32_t sBu[2] = {sAu + kABytes, sAu + kABytes + kBChunkBytes};

    int tid  = threadIdx.x;
    int wid  = tid >> 5, lane = tid & 31;
    int g    = lane >> 2;          // 0..7
    int t2   = (lane & 3) * 2;     // 0,2,4,6
    int wm   = wid & 1;            // 2 warps along M
    int wn   = wid >> 1;           // 4 warps along N

    int ngrp  = blockIdx.x;        // 0..10
    int mtile = blockIdx.y;        // 0..31
    int b     = blockIdx.z;        // 0..1
    int ns = min(kNSUB, kNT - ngrp * kNSUB);
    int nchunks = ns * 4;

    // ---- load full A tile (128 x 256 halves) + first two B chunks ----
    {
        const __half* srcA = g_f1h + ((size_t)b * kM + (size_t)mtile * 128) * kC;
        #pragma unroll
        for (int j = 0; j < 16; j++) {
            int i = tid + j * 256;          // 4096 x 16B
            int r = i >> 5, seg = i & 31;
            cp16(sAu + r * (kAStrideH * 2) + seg * 16, srcA + (size_t)r * kC + seg * 8);
        }
        issueB(sBu[0], tid, b, (ngrp * kNSUB + 0) * 128, 0);
        cp_commit();                         // g0 = A + chunk0
        issueB(sBu[1], tid, b, (ngrp * kNSUB + 0) * 128, 1);
        cp_commit();                         // g1 = chunk1
    }

    float acc[4][4][4];
    #pragma unroll
    for (int mf = 0; mf < 4; mf++)
        #pragma unroll
        for (int nf = 0; nf < 4; nf++)
            #pragma unroll
            for (int i = 0; i < 4; i++) acc[mf][nf][i] = 0.0f;

    for (int j = 0; j < nchunks; j++) {
        if (j == nchunks - 1) cp_wait0(); else cp_wait1();
        __syncthreads();

        uint32_t sBc = sBu[j & 1];
        int kc = j & 3;

        #pragma unroll
        for (int ks = 0; ks < 4; ks++) {
            int kg = kc * 64 + ks * 16;      // global k within 256
            uint32_t af[4][4], bf[4][2];
            #pragma unroll
            for (int mf = 0; mf < 4; mf++) {
                int r = wm * 64 + mf * 16 + g;
                uint32_t base = sAu + (kg + t2) * 2;
                af[mf][0] = *reinterpret_cast<const uint32_t*>(smA + (r    ) * (kAStrideH*2) + (kg + t2) * 2 - 0 + 0 + ((char*)0 - (char*)0));
                af[mf][0] = *reinterpret_cast<const uint32_t*>(smA + (r    ) * (kAStrideH*2) + (kg     + t2) * 2);
                af[mf][1] = *reinterpret_cast<const uint32_t*>(smA + (r + 8) * (kAStrideH*2) + (kg     + t2) * 2);
                af[mf][2] = *reinterpret_cast<const uint32_t*>(smA + (r    ) * (kAStrideH*2) + (kg + 8 + t2) * 2);
                af[mf][3] = *reinterpret_cast<const uint32_t*>(smA + (r + 8) * (kAStrideH*2) + (kg + 8 + t2) * 2);
                (void)base;
            }
            char* smBc = smem + kABytes + (j & 1) * kBChunkBytes;
            #pragma unroll
            for (int nf = 0; nf < 4; nf++) {
                int n = wn * 32 + nf * 8 + g;
                bf[nf][0] = *reinterpret_cast<const uint32_t*>(smBc + n * (kBStrideH*2) + (ks * 16     + t2) * 2);
                bf[nf][1] = *reinterpret_cast<const uint32_t*>(smBc + n * (kBStrideH*2) + (ks * 16 + 8 + t2) * 2);
            }
            #pragma unroll
            for (int mf = 0; mf < 4; mf++)
                #pragma unroll
                for (int nf = 0; nf < 4; nf++)
                    mma16816(acc[mf][nf], af[mf], bf[nf]);
        }
        __syncthreads();

        if (j + 2 < nchunks) {
            int jn = j + 2;
            issueB(sBu[jn & 1], tid, b, (ngrp * kNSUB + (jn >> 2)) * 128, jn & 3);
            cp_commit();
        }

        if ((j & 3) == 3) {
            // epilogue for subtile s = j>>2
            int s = j >> 2;
            int pbase = (ngrp * kNSUB + s) * 128 + wn * 32;
            #pragma unroll
            for (int mf = 0; mf < 4; mf++) {
                int m0 = mtile * 128 + wm * 64 + mf * 16 + g;
                float* row0 = g_corr + ((size_t)b * kM + m0) * kPPad + pbase;
                float* row1 = row0 + 8 * kPPad;
                #pragma unroll
                for (int nf = 0; nf < 4; nf++) {
                    float2 v01 = make_float2(acc[mf][nf][0], acc[mf][nf][1]);
                    float2 v23 = make_float2(acc[mf][nf][2], acc[mf][nf][3]);
                    *reinterpret_cast<float2*>(row0 + nf * 8 + t2) = v01;
                    *reinterpret_cast<float2*>(row1 + nf * 8 + t2) = v23;
                    acc[mf][nf][0] = 0.0f; acc[mf][nf][1] = 0.0f;
                    acc[mf][nf][2] = 0.0f; acc[mf][nf][3] = 0.0f;
                }
            }
        }
    }
}

// ---------------------------------------------------------------------------
// Kernel 5: sample scalar taps from fp32 corr, bilinear combine, store output
// ---------------------------------------------------------------------------
__global__ void __launch_bounds__(128) k_sample(const float* __restrict__ coords,
                                                float* __restrict__ out) {
    int q = blockIdx.x;
    int b = q >> 12;
    int m = q & (kM - 1);
    int tid = threadIdx.x;

    __shared__ float Dsh[100];

    float clx = coords[(size_t)q * 2 + 0];
    float cly = coords[(size_t)q * 2 + 1];
    const float* crow = g_corr + (size_t)q * kPPad;

    for (int l = 0; l < kLevels; l++) {
        int Wl = kW >> l, Hl = kH >> l;
        float fx0 = floorf(clx), fy0 = floorf(cly);
        int ix0 = (int)fx0 - kRad;
        int iy0 = (int)fy0 - kRad;
        float wx1 = clx - fx0, wx0 = 1.0f - wx1;
        float wy1 = cly - fy0, wy0 = 1.0f - wy1;

        if (tid < 100) {
            int py = tid / 10, px = tid - py * 10;
            int txp = ix0 + px, typ = iy0 + py;
            float v = 0.0f;
            if ((unsigned)txp < (unsigned)Wl && (unsigned)typ < (unsigned)Hl)
                v = crow[c_lvl_off[l] + typ * Wl + txp];
            Dsh[tid] = v;
        }
        __syncthreads();

        if (tid < 81) {
            int ixo = tid / 9;
            int iyo = tid - ixo * 9;
            float d00 = Dsh[iyo * 10 + ixo];
            float d01 = Dsh[iyo * 10 + ixo + 1];
            float d10 = Dsh[iyo * 10 + ixo + 10];
            float d11 = Dsh[iyo * 10 + ixo + 11];
            float val = wy0 * (wx0 * d00 + wx1 * d01) + wy1 * (wx0 * d10 + wx1 * d11);
            out[((size_t)b * kFeat + l * 81 + tid) * kM + m] = val;
        }
        __syncthreads();

        clx *= 0.5f;
        cly *= 0.5f;
    }
}

// ---------------------------------------------------------------------------
extern "C" void kernel_launch(void* const* d_in, const int* in_sizes, int n_in,
                              void* d_out, int out_size) {
    const float* fmap1  = (const float*)d_in[0];
    const float* fmap2  = (const float*)d_in[1];
    const float* coords = (const float*)d_in[2];
    float* out = (float*)d_out;

    // Build transposed fp16 pyramid of fmap2 + fp16 fmap1
    k_transpose<<<kB * kH * 2 * 8, dim3(32, 32)>>>(fmap2);
    for (int l = 1; l < kLevels; l++) {
        int Wl = kW >> l;
        int n = kB * Wl * Wl * kC;
        k_pool<<<(n + 255) / 256, 256>>>(l, n);
    }
    k_f1cvt<<<2048, 256>>>((const float4*)fmap1);

    // Correlation pyramid via HMMA GEMM (baseline mma.sync — no 'a'-gated PTX)
    cudaFuncSetAttribute(k_gemm, cudaFuncAttributeMaxDynamicSharedMemorySize, kGemmSmem);
    k_gemm<<<dim3(kNGRP, kM / 128, kB), 256, kGemmSmem>>>();

    // Scalar-tap sampling
    k_sample<<<kB * kM, 128>>>(coords, out);
}

// round 11
// speedup vs baseline: 1.4642x; 1.0129x over previous
#include <cuda_runtime.h>
#include <cuda_fp16.h>
#include <cstdint>

// ---------------------------------------------------------------------------
// Problem constants
// ---------------------------------------------------------------------------
constexpr int kB = 2;
constexpr int kM = 4096;
constexpr int kC = 256;
constexpr int kH = 64;
constexpr int kW = 64;
constexpr int kLevels = 4;
constexpr int kRad = 4;
constexpr int kSide = 9;
constexpr int kFeat = kLevels * kSide * kSide;          // 324
constexpr int kP    = 4096 + 1024 + 256 + 64;           // 5440 positions / batch
constexpr int kPPad = 5504;                             // 43 * 128
constexpr int kNT   = 43;                               // N tiles of 128
constexpr int kNSUB = 4;                                // N tiles per CTA
constexpr int kNGRP = 11;                               // ceil(43/4)

// Static device scratch (zero-initialized; g_pyrh pad rows stay zero)
__device__ float  g_pyrf[(size_t)kB * kPPad * kC];      // fp32 level-0 (pool source)
__device__ __half g_pyrh[(size_t)kB * kPPad * kC];      // fp16 GEMM B operand (all levels)
__device__ __half g_f1h [(size_t)kB * kM * kC];         // fp16 GEMM A operand
__device__ __half g_corr[(size_t)kB * kM * kPPad];      // fp16 correlation pyramid

__constant__ int c_lvl_off[4] = {0, 4096, 5120, 5376};

// ---------------------------------------------------------------------------
// Helpers (baseline PTX only — nothing 'a'-gated; ptxas targets sm_103)
// ---------------------------------------------------------------------------
__device__ __forceinline__ uint32_t smem_u32(const void* p) {
    uint32_t a;
    asm("{ .reg .u64 t; cvta.to.shared.u64 t, %1; cvt.u32.u64 %0, t; }" : "=r"(a) : "l"(p));
    return a;
}
__device__ __forceinline__ void cp16(uint32_t dst, const void* src) {
    asm volatile("cp.async.cg.shared.global [%0], [%1], 16;" :: "r"(dst), "l"(src));
}
__device__ __forceinline__ void cp_commit() { asm volatile("cp.async.commit_group;" ::: "memory"); }
__device__ __forceinline__ void cp_wait1()  { asm volatile("cp.async.wait_group 1;" ::: "memory"); }
__device__ __forceinline__ void cp_wait0()  { asm volatile("cp.async.wait_group 0;" ::: "memory"); }
__device__ __forceinline__ void mma16816(float* c, const uint32_t* a, const uint32_t* b) {
    asm volatile(
        "mma.sync.aligned.m16n8k16.row.col.f32.f16.f16.f32 "
        "{%0,%1,%2,%3}, {%4,%5,%6,%7}, {%8,%9}, {%0,%1,%2,%3};"
        : "+f"(c[0]), "+f"(c[1]), "+f"(c[2]), "+f"(c[3])
        : "r"(a[0]), "r"(a[1]), "r"(a[2]), "r"(a[3]), "r"(b[0]), "r"(b[1]));
}
__device__ __forceinline__ void ldm_x4(uint32_t* r, uint32_t addr) {
    asm volatile("ldmatrix.sync.aligned.m8n8.x4.shared.b16 {%0,%1,%2,%3}, [%4];"
                 : "=r"(r[0]), "=r"(r[1]), "=r"(r[2]), "=r"(r[3]) : "r"(addr));
}

// ---------------------------------------------------------------------------
// Kernel 1: transpose fmap2 (B,C,H,W) -> (B, pos, C), fp32 + fp16 level 0
// ---------------------------------------------------------------------------
__global__ void k_transpose(const float* __restrict__ fmap2) {
    __shared__ float s[32][33];
    int bidx = blockIdx.x;
    int ct = bidx & 7;  bidx >>= 3;
    int xt = bidx & 1;  bidx >>= 1;
    int y  = bidx & 63; bidx >>= 6;
    int b  = bidx;
    int tx = threadIdx.x, ty = threadIdx.y;
    s[ty][tx] = fmap2[(((size_t)b * kC + ct * 32 + ty) * kH + y) * kW + (xt * 32 + tx)];
    __syncthreads();
    float v = s[tx][ty];
    size_t o = ((size_t)b * kPPad + (size_t)y * kW + (xt * 32 + ty)) * kC + (ct * 32 + tx);
    g_pyrf[o] = v;
    g_pyrh[o] = __float2half(v);
}

// ---------------------------------------------------------------------------
// Kernel 2 (fused): build pyramid levels 1..3 in one launch.
// Block = one 16x16 level-0 tile x 32 channels; pools 8x8 -> 4x4 -> 2x2 in
// smem (fp32 chain), writes fp16 to g_pyrh only. Grid 256, block 256.
// ---------------------------------------------------------------------------
__global__ void __launch_bounds__(256) k_pool_fused() {
    __shared__ float s0[256][33];
    __shared__ float s1[64][33];
    __shared__ float s2[16][33];

    int bidx = blockIdx.x;
    int cc = bidx & 7;  bidx >>= 3;
    int xt = bidx & 3;  bidx >>= 2;
    int yt = bidx & 3;  bidx >>= 2;
    int b  = bidx;
    int tid = threadIdx.x;

    // load 16x16 level-0 positions x 32 channels (float4 per 8-thread group)
    const float* src = g_pyrf + ((size_t)b * kPPad) * kC + cc * 32;
    #pragma unroll
    for (int j = 0; j < 8; j++) {
        int idx = tid + j * 256;        // 2048 float4s
        int pos = idx >> 3, cseg = idx & 7;
        int py = pos >> 4, px = pos & 15;
        const float4 v = *reinterpret_cast<const float4*>(
            src + ((size_t)(yt * 16 + py) * kW + (xt * 16 + px)) * kC + cseg * 4);
        s0[pos][cseg * 4 + 0] = v.x;
        s0[pos][cseg * 4 + 1] = v.y;
        s0[pos][cseg * 4 + 2] = v.z;
        s0[pos][cseg * 4 + 3] = v.w;
    }
    __syncthreads();

    // level 1: 8x8 x 32ch
    {
        int pos1 = tid >> 2;            // 0..63
        int c0 = (tid & 3) * 8;
        int y1 = pos1 >> 3, x1 = pos1 & 7;
        int pa = (2 * y1) * 16 + 2 * x1;
        __half h[8];
        #pragma unroll
        for (int c = 0; c < 8; c++) {
            float v = 0.25f * (s0[pa][c0 + c] + s0[pa + 1][c0 + c] +
                               s0[pa + 16][c0 + c] + s0[pa + 17][c0 + c]);
            s1[pos1][c0 + c] = v;
            h[c] = __float2half(v);
        }
        size_t o = ((size_t)b * kPPad + 4096 + (size_t)(yt * 8 + y1) * 32 + (xt * 8 + x1)) * kC
                 + cc * 32 + c0;
        *reinterpret_cast<uint4*>(g_pyrh + o) = *reinterpret_cast<uint4*>(h);
    }
    __syncthreads();

    // level 2: 4x4 x 32ch (128 threads)
    if (tid < 128) {
        int pos2 = tid >> 3;            // 0..15
        int c0 = (tid & 7) * 4;
        int y2 = pos2 >> 2, x2 = pos2 & 3;
        int pa = (2 * y2) * 8 + 2 * x2;
        __half h[4];
        #pragma unroll
        for (int c = 0; c < 4; c++) {
            float v = 0.25f * (s1[pa][c0 + c] + s1[pa + 1][c0 + c] +
                               s1[pa + 8][c0 + c] + s1[pa + 9][c0 + c]);
            s2[pos2][c0 + c] = v;
            h[c] = __float2half(v);
        }
        size_t o = ((size_t)b * kPPad + 5120 + (size_t)(yt * 4 + y2) * 16 + (xt * 4 + x2)) * kC
                 + cc * 32 + c0;
        *reinterpret_cast<uint2*>(g_pyrh + o) = *reinterpret_cast<uint2*>(h);
    }
    __syncthreads();

    // level 3: 2x2 x 32ch (128 threads, one half each)
    if (tid < 128) {
        int pos3 = tid >> 5;            // 0..3
        int c = tid & 31;
        int y3 = pos3 >> 1, x3 = pos3 & 1;
        int pa = (2 * y3) * 4 + 2 * x3;
        float v = 0.25f * (s2[pa][c] + s2[pa + 1][c] + s2[pa + 4][c] + s2[pa + 5][c]);
        size_t o = ((size_t)b * kPPad + 5376 + (size_t)(yt * 2 + y3) * 8 + (xt * 2 + x3)) * kC
                 + cc * 32 + c;
        g_pyrh[o] = __float2half(v);
    }
}

// ---------------------------------------------------------------------------
// Kernel 3: fmap1 fp32 -> fp16
// ---------------------------------------------------------------------------
__global__ void k_f1cvt(const float4* __restrict__ f1) {
    int i = blockIdx.x * blockDim.x + threadIdx.x;
    float4 v = f1[i];
    __half2 a = __floats2half2_rn(v.x, v.y);
    __half2 b = __floats2half2_rn(v.z, v.w);
    uint2 u;
    u.x = *reinterpret_cast<uint32_t*>(&a);
    u.y = *reinterpret_cast<uint32_t*>(&b);
    reinterpret_cast<uint2*>(g_f1h)[i] = u;
}

// ---------------------------------------------------------------------------
// Kernel 4: HMMA GEMM  corr[b, m, p] = sum_c f1h[b,m,c] * pyrh[b,p,c]
// CTA: M=128 (K=256 of A resident), up to 4 N-subtiles of 128, cp.async
// double-buffered B chunks (64 k each). ldmatrix fragment loads.
// 2 CTAs/SM (smem 2x104448 = 209KB).
// ---------------------------------------------------------------------------
constexpr int kAStrideH = 264;                 // 256 + 8 pad (halves), row 528B
constexpr int kABytes   = 128 * kAStrideH * 2; // 67584
constexpr int kBStrideH = 72;                  // 64 + 8 pad (halves), row 144B
constexpr int kBChunkBytes = 128 * kBStrideH * 2;  // 18432
constexpr int kGemmSmem = kABytes + 2 * kBChunkBytes;  // 104448

__device__ __forceinline__ void issueB(uint32_t sB, int tid, int b, int pbase, int kc) {
    const __half* src0 = g_pyrh + ((size_t)b * kPPad + pbase) * kC + kc * 64;
    #pragma unroll
    for (int j = 0; j < 4; j++) {
        int i = tid + j * 256;          // 1024 x 16B
        int n = i >> 3, seg = i & 7;
        cp16(sB + n * (kBStrideH * 2) + seg * 16, src0 + (size_t)n * kC + seg * 8);
    }
}

__global__ void __launch_bounds__(256, 2) k_gemm() {
    extern __shared__ char smem[];
    uint32_t sAu = smem_u32(smem);
    uint32_t sBu[2] = {sAu + kABytes, sAu + kABytes + kBChunkBytes};

    int tid  = threadIdx.x;
    int wid  = tid >> 5, lane = tid & 31;
    int g    = lane >> 2;
    int t2   = (lane & 3) * 2;
    int wm   = wid & 1;                 // 2 warps along M
    int wn   = wid >> 1;                // 4 warps along N

    int ngrp  = blockIdx.x;
    int mtile = blockIdx.y;
    int b     = blockIdx.z;
    int ns = min(kNSUB, kNT - ngrp * kNSUB);
    int nchunks = ns * 4;

    // ldmatrix lane address components
    int lrow = (lane & 7) + ((lane >> 3) & 1) * 8;  // row within 16
    int lk16 = ((lane >> 4) & 1) * 16;              // byte offset: +8 halves
    uint32_t aOff[4];
    #pragma unroll
    for (int mf = 0; mf < 4; mf++)
        aOff[mf] = sAu + (wm * 64 + mf * 16 + lrow) * (kAStrideH * 2) + lk16;
    uint32_t bOff[2];
    #pragma unroll
    for (int np = 0; np < 2; np++)
        bOff[np] = (wn * 32 + np * 16 + lrow) * (kBStrideH * 2) + lk16;

    // ---- load full A tile + first two B chunks ----
    {
        const __half* srcA = g_f1h + ((size_t)b * kM + (size_t)mtile * 128) * kC;
        #pragma unroll
        for (int j = 0; j < 16; j++) {
            int i = tid + j * 256;
            int r = i >> 5, seg = i & 31;
            cp16(sAu + r * (kAStrideH * 2) + seg * 16, srcA + (size_t)r * kC + seg * 8);
        }
        issueB(sBu[0], tid, b, (ngrp * kNSUB) * 128, 0);
        cp_commit();
        issueB(sBu[1], tid, b, (ngrp * kNSUB) * 128, 1);
        cp_commit();
    }

    float acc[4][4][4];
    #pragma unroll
    for (int mf = 0; mf < 4; mf++)
        #pragma unroll
        for (int nf = 0; nf < 4; nf++)
            #pragma unroll
            for (int i = 0; i < 4; i++) acc[mf][nf][i] = 0.0f;

    for (int j = 0; j < nchunks; j++) {
        if (j == nchunks - 1) cp_wait0(); else cp_wait1();
        __syncthreads();

        uint32_t sBc = sBu[j & 1];
        int kc = j & 3;

        #pragma unroll
        for (int ks = 0; ks < 4; ks++) {
            int kg2 = (kc * 64 + ks * 16) * 2;
            uint32_t af[4][4], bq[2][4];
            #pragma unroll
            for (int mf = 0; mf < 4; mf++) ldm_x4(af[mf], aOff[mf] + kg2);
            #pragma unroll
            for (int np = 0; np < 2; np++) ldm_x4(bq[np], sBc + bOff[np] + ks * 32);
            #pragma unroll
            for (int mf = 0; mf < 4; mf++)
                #pragma unroll
                for (int nf = 0; nf < 4; nf++) {
                    uint32_t bfr[2] = {bq[nf >> 1][nf & 1], bq[nf >> 1][2 + (nf & 1)]};
                    mma16816(acc[mf][nf], af[mf], bfr);
                }
        }
        __syncthreads();

        if (j + 2 < nchunks) {
            int jn = j + 2;
            issueB(sBu[jn & 1], tid, b, (ngrp * kNSUB + (jn >> 2)) * 128, jn & 3);
            cp_commit();
        }

        if ((j & 3) == 3) {
            // epilogue for subtile s = j>>2, fp16 stores
            int s = j >> 2;
            int pbase = (ngrp * kNSUB + s) * 128 + wn * 32;
            #pragma unroll
            for (int mf = 0; mf < 4; mf++) {
                int m0 = mtile * 128 + wm * 64 + mf * 16 + g;
                __half* row0 = g_corr + ((size_t)b * kM + m0) * kPPad + pbase;
                __half* row1 = row0 + 8 * kPPad;
                #pragma unroll
                for (int nf = 0; nf < 4; nf++) {
                    __half2 v01 = __floats2half2_rn(acc[mf][nf][0], acc[mf][nf][1]);
                    __half2 v23 = __floats2half2_rn(acc[mf][nf][2], acc[mf][nf][3]);
                    *reinterpret_cast<__half2*>(row0 + nf * 8 + t2) = v01;
                    *reinterpret_cast<__half2*>(row1 + nf * 8 + t2) = v23;
                    acc[mf][nf][0] = 0.0f; acc[mf][nf][1] = 0.0f;
                    acc[mf][nf][2] = 0.0f; acc[mf][nf][3] = 0.0f;
                }
            }
        }
    }
}

// ---------------------------------------------------------------------------
// Kernel 5: sample taps from fp16 corr. Block = 32 queries x 128 threads.
// Taps staged in smem; output written with qlocal-contiguous lanes ->
// fully coalesced 128B stores.
// ---------------------------------------------------------------------------
__global__ void __launch_bounds__(128) k_sample(const float* __restrict__ coords,
                                                float* __restrict__ out) {
    __shared__ float Dsh[32][101];      // odd stride -> conflict-free columns
    __shared__ float cxs[32], cys[32];

    int qt = blockIdx.x;                // 0..255
    int b  = qt >> 7;
    int m0 = (qt & 127) * 32;
    int tid = threadIdx.x;
    int qlocal = tid & 31;
    int sub    = tid >> 5;              // 0..3

    if (tid < 32) {
        int q = b * kM + m0 + tid;
        cxs[tid] = coords[(size_t)q * 2 + 0];
        cys[tid] = coords[(size_t)q * 2 + 1];
    }
    __syncthreads();

    float clx = cxs[qlocal];
    float cly = cys[qlocal];
    const __half* crow = g_corr + (size_t)(b * kM + m0 + qlocal) * kPPad;

    for (int l = 0; l < kLevels; l++) {
        int Wl = kW >> l, Hl = kH >> l;
        float fx0 = floorf(clx), fy0 = floorf(cly);
        int ix0 = (int)fx0 - kRad;
        int iy0 = (int)fy0 - kRad;
        float wx1 = clx - fx0, wx0 = 1.0f - wx1;
        float wy1 = cly - fy0, wy0 = 1.0f - wy1;

        // load 25 taps per thread (4 subs cover 100)
        #pragma unroll 5
        for (int i = 0; i < 25; i++) {
            int p = sub * 25 + i;
            int py = p / 10, px = p - py * 10;
            int txp = ix0 + px, typ = iy0 + py;
            float v = 0.0f;
            if ((unsigned)txp < (unsigned)Wl && (unsigned)typ < (unsigned)Hl)
                v = __half2float(crow[c_lvl_off[l] + typ * Wl + txp]);
            Dsh[qlocal][p] = v;
        }
        __syncthreads();

        // combine + coalesced store: warp handles one feature across 32 queries
        #pragma unroll
        for (int it = 0; it < 21; it++) {
            int f = it * 4 + sub;
            if (f < 81) {
                int ixo = f / 9;
                int iyo = f - ixo * 9;
                float d00 = Dsh[qlocal][iyo * 10 + ixo];
                float d01 = Dsh[qlocal][iyo * 10 + ixo + 1];
                float d10 = Dsh[qlocal][iyo * 10 + ixo + 10];
                float d11 = Dsh[qlocal][iyo * 10 + ixo + 11];
                float val = wy0 * (wx0 * d00 + wx1 * d01) + wy1 * (wx0 * d10 + wx1 * d11);
                out[((size_t)b * kFeat + l * 81 + f) * kM + m0 + qlocal] = val;
            }
        }
        __syncthreads();

        clx *= 0.5f;
        cly *= 0.5f;
    }
}

// ---------------------------------------------------------------------------
extern "C" void kernel_launch(void* const* d_in, const int* in_sizes, int n_in,
                              void* d_out, int out_size) {
    const float* fmap1  = (const float*)d_in[0];
    const float* fmap2  = (const float*)d_in[1];
    const float* coords = (const float*)d_in[2];
    float* out = (float*)d_out;

    k_f1cvt<<<2048, 256>>>((const float4*)fmap1);
    k_transpose<<<kB * kH * 2 * 8, dim3(32, 32)>>>(fmap2);
    k_pool_fused<<<256, 256>>>();

    cudaFuncSetAttribute(k_gemm, cudaFuncAttributeMaxDynamicSharedMemorySize, kGemmSmem);
    k_gemm<<<dim3(kNGRP, kM / 128, kB), 256, kGemmSmem>>>();

    k_sample<<<256, 128>>>(coords, out);
}

// round 12
// speedup vs baseline: 1.5802x; 1.0793x over previous
#include <cuda_runtime.h>
#include <cuda_fp16.h>
#include <cstdint>

// ---------------------------------------------------------------------------
// Problem constants
// ---------------------------------------------------------------------------
constexpr int kB = 2;
constexpr int kM = 4096;
constexpr int kC = 256;
constexpr int kH = 64;
constexpr int kW = 64;
constexpr int kLevels = 4;
constexpr int kRad = 4;
constexpr int kSide = 9;
constexpr int kFeat = kLevels * kSide * kSide;          // 324
constexpr int kP    = 4096 + 1024 + 256 + 64;           // 5440 positions / batch
constexpr int kPPad = 5504;                             // 43 * 128
constexpr int kNT   = 43;                               // N tiles of 128
constexpr int kNSUB = 2;                                // N tiles per CTA
constexpr int kNGRP = 22;                               // ceil(43/2)

// Static device scratch (zero-initialized; g_pyrh pad rows stay zero)
__device__ float  g_pyrf[(size_t)kB * kPPad * kC];      // fp32 level-0 (pool source)
__device__ __half g_pyrh[(size_t)kB * kPPad * kC];      // fp16 GEMM B operand (all levels)
__device__ __half g_f1h [(size_t)kB * kM * kC];         // fp16 GEMM A operand
__device__ __half g_corr[(size_t)kB * kM * kPPad];      // fp16 correlation pyramid

__constant__ int c_lvl_off[4] = {0, 4096, 5120, 5376};

// ---------------------------------------------------------------------------
// Helpers (baseline PTX only — nothing 'a'-gated; ptxas targets sm_103)
// ---------------------------------------------------------------------------
__device__ __forceinline__ uint32_t smem_u32(const void* p) {
    uint32_t a;
    asm("{ .reg .u64 t; cvta.to.shared.u64 t, %1; cvt.u32.u64 %0, t; }" : "=r"(a) : "l"(p));
    return a;
}
__device__ __forceinline__ void cp16(uint32_t dst, const void* src) {
    asm volatile("cp.async.cg.shared.global [%0], [%1], 16;" :: "r"(dst), "l"(src));
}
__device__ __forceinline__ void cp_commit() { asm volatile("cp.async.commit_group;" ::: "memory"); }
__device__ __forceinline__ void cp_wait1()  { asm volatile("cp.async.wait_group 1;" ::: "memory"); }
__device__ __forceinline__ void cp_wait0()  { asm volatile("cp.async.wait_group 0;" ::: "memory"); }
__device__ __forceinline__ void mma16816(float* c, const uint32_t* a, const uint32_t* b) {
    asm volatile(
        "mma.sync.aligned.m16n8k16.row.col.f32.f16.f16.f32 "
        "{%0,%1,%2,%3}, {%4,%5,%6,%7}, {%8,%9}, {%0,%1,%2,%3};"
        : "+f"(c[0]), "+f"(c[1]), "+f"(c[2]), "+f"(c[3])
        : "r"(a[0]), "r"(a[1]), "r"(a[2]), "r"(a[3]), "r"(b[0]), "r"(b[1]));
}
__device__ __forceinline__ void ldm_x4(uint32_t* r, uint32_t addr) {
    asm volatile("ldmatrix.sync.aligned.m8n8.x4.shared.b16 {%0,%1,%2,%3}, [%4];"
                 : "=r"(r[0]), "=r"(r[1]), "=r"(r[2]), "=r"(r[3]) : "r"(addr));
}

// ---------------------------------------------------------------------------
// Kernel 1 (fused): transpose fmap2 (B,C,H,W) -> (B,pos,C) fp32+fp16 level 0,
// AND fmap1 fp32 -> fp16 (blocks >= 2048 do the convert).
// ---------------------------------------------------------------------------
__global__ void k_prep(const float* __restrict__ fmap2, const float4* __restrict__ f1) {
    if (blockIdx.x >= 2048) {
        int i = (blockIdx.x - 2048) * 1024 + threadIdx.y * 32 + threadIdx.x;
        float4 v = f1[i];
        __half2 a = __floats2half2_rn(v.x, v.y);
        __half2 b = __floats2half2_rn(v.z, v.w);
        uint2 u;
        u.x = *reinterpret_cast<uint32_t*>(&a);
        u.y = *reinterpret_cast<uint32_t*>(&b);
        reinterpret_cast<uint2*>(g_f1h)[i] = u;
        return;
    }
    __shared__ float s[32][33];
    int bidx = blockIdx.x;
    int ct = bidx & 7;  bidx >>= 3;
    int xt = bidx & 1;  bidx >>= 1;
    int y  = bidx & 63; bidx >>= 6;
    int b  = bidx;
    int tx = threadIdx.x, ty = threadIdx.y;
    s[ty][tx] = fmap2[(((size_t)b * kC + ct * 32 + ty) * kH + y) * kW + (xt * 32 + tx)];
    __syncthreads();
    float v = s[tx][ty];
    size_t o = ((size_t)b * kPPad + (size_t)y * kW + (xt * 32 + ty)) * kC + (ct * 32 + tx);
    g_pyrf[o] = v;
    g_pyrh[o] = __float2half(v);
}

// ---------------------------------------------------------------------------
// Kernel 2 (fused): build pyramid levels 1..3 in one launch.
// ---------------------------------------------------------------------------
__global__ void __launch_bounds__(256) k_pool_fused() {
    __shared__ float s0[256][33];
    __shared__ float s1[64][33];
    __shared__ float s2[16][33];

    int bidx = blockIdx.x;
    int cc = bidx & 7;  bidx >>= 3;
    int xt = bidx & 3;  bidx >>= 2;
    int yt = bidx & 3;  bidx >>= 2;
    int b  = bidx;
    int tid = threadIdx.x;

    const float* src = g_pyrf + ((size_t)b * kPPad) * kC + cc * 32;
    #pragma unroll
    for (int j = 0; j < 8; j++) {
        int idx = tid + j * 256;
        int pos = idx >> 3, cseg = idx & 7;
        int py = pos >> 4, px = pos & 15;
        const float4 v = *reinterpret_cast<const float4*>(
            src + ((size_t)(yt * 16 + py) * kW + (xt * 16 + px)) * kC + cseg * 4);
        s0[pos][cseg * 4 + 0] = v.x;
        s0[pos][cseg * 4 + 1] = v.y;
        s0[pos][cseg * 4 + 2] = v.z;
        s0[pos][cseg * 4 + 3] = v.w;
    }
    __syncthreads();

    {
        int pos1 = tid >> 2;
        int c0 = (tid & 3) * 8;
        int y1 = pos1 >> 3, x1 = pos1 & 7;
        int pa = (2 * y1) * 16 + 2 * x1;
        __half h[8];
        #pragma unroll
        for (int c = 0; c < 8; c++) {
            float v = 0.25f * (s0[pa][c0 + c] + s0[pa + 1][c0 + c] +
                               s0[pa + 16][c0 + c] + s0[pa + 17][c0 + c]);
            s1[pos1][c0 + c] = v;
            h[c] = __float2half(v);
        }
        size_t o = ((size_t)b * kPPad + 4096 + (size_t)(yt * 8 + y1) * 32 + (xt * 8 + x1)) * kC
                 + cc * 32 + c0;
        *reinterpret_cast<uint4*>(g_pyrh + o) = *reinterpret_cast<uint4*>(h);
    }
    __syncthreads();

    if (tid < 128) {
        int pos2 = tid >> 3;
        int c0 = (tid & 7) * 4;
        int y2 = pos2 >> 2, x2 = pos2 & 3;
        int pa = (2 * y2) * 8 + 2 * x2;
        __half h[4];
        #pragma unroll
        for (int c = 0; c < 4; c++) {
            float v = 0.25f * (s1[pa][c0 + c] + s1[pa + 1][c0 + c] +
                               s1[pa + 8][c0 + c] + s1[pa + 9][c0 + c]);
            s2[pos2][c0 + c] = v;
            h[c] = __float2half(v);
        }
        size_t o = ((size_t)b * kPPad + 5120 + (size_t)(yt * 4 + y2) * 16 + (xt * 4 + x2)) * kC
                 + cc * 32 + c0;
        *reinterpret_cast<uint2*>(g_pyrh + o) = *reinterpret_cast<uint2*>(h);
    }
    __syncthreads();

    if (tid < 128) {
        int pos3 = tid >> 5;
        int c = tid & 31;
        int y3 = pos3 >> 1, x3 = pos3 & 1;
        int pa = (2 * y3) * 4 + 2 * x3;
        float v = 0.25f * (s2[pa][c] + s2[pa + 1][c] + s2[pa + 4][c] + s2[pa + 5][c]);
        size_t o = ((size_t)b * kPPad + 5376 + (size_t)(yt * 2 + y3) * 8 + (xt * 2 + x3)) * kC
                 + cc * 32 + c;
        g_pyrh[o] = __float2half(v);
    }
}

// ---------------------------------------------------------------------------
// Kernel 3: HMMA GEMM  corr[b, m, p] = sum_c f1h[b,m,c] * pyrh[b,p,c]
// A tile 128x256 resident (XOR-swizzled, 64KB exact). B: 3-stage ring of
// 128x64k XOR-swizzled 16KB chunks. ONE syncthreads per chunk, prefetch
// distance 2. 2 N-subtiles per CTA (grid 1408 -> ~95% wave utilization).
// 2 CTAs/SM (smem 114688/CTA).
// ---------------------------------------------------------------------------
constexpr int kABytes = 128 * 512;                      // 65536, swizzled
constexpr int kBChunkBytes = 128 * 128;                 // 16384, swizzled
constexpr int kGemmSmem = kABytes + 3 * kBChunkBytes;   // 114688

// A smem: row r (0..127) x 512B; 16B unit u (0..31): phys = r*512 + ((u^(r&7))<<4)
// B smem: row n (0..127) x 128B; 16B unit u (0..7):  phys = n*128 + ((u^(n&7))<<4)

__device__ __forceinline__ void issueB(uint32_t sB, int tid, int b, int pbase, int kc) {
    const __half* src0 = g_pyrh + ((size_t)b * kPPad + pbase) * kC + kc * 64;
    #pragma unroll
    for (int j = 0; j < 4; j++) {
        int i = tid + j * 256;          // 1024 x 16B
        int n = i >> 3, seg = i & 7;
        cp16(sB + n * 128 + ((seg ^ (n & 7)) << 4), src0 + (size_t)n * kC + seg * 8);
    }
}

__global__ void __launch_bounds__(256, 2) k_gemm() {
    extern __shared__ char smem[];
    uint32_t sAu = smem_u32(smem);
    uint32_t sBu[3] = {sAu + kABytes, sAu + kABytes + kBChunkBytes,
                       sAu + kABytes + 2 * kBChunkBytes};

    int tid  = threadIdx.x;
    int wid  = tid >> 5, lane = tid & 31;
    int g    = lane >> 2;
    int t2   = (lane & 3) * 2;
    int wm   = wid & 1;                 // 2 warps along M
    int wn   = wid >> 1;                // 4 warps along N

    int ngrp  = blockIdx.x;             // 0..21
    int mtile = blockIdx.y;             // 0..31
    int b     = blockIdx.z;             // 0..1
    int ns = min(kNSUB, kNT - ngrp * kNSUB);
    int nchunks = ns * 4;

    // ldmatrix lane row + k-half selector
    int lrow  = (lane & 7) + ((lane >> 3) & 1) * 8;
    int ulane = (lane >> 4) & 1;

    uint32_t aRow[4]; int aX[4];
    #pragma unroll
    for (int mf = 0; mf < 4; mf++) {
        int r = wm * 64 + mf * 16 + lrow;
        aRow[mf] = sAu + r * 512;
        aX[mf] = r & 7;
    }
    uint32_t bRow[2]; int bX[2];
    #pragma unroll
    for (int np = 0; np < 2; np++) {
        int n = wn * 32 + np * 16 + lrow;
        bRow[np] = n * 128;
        bX[np] = n & 7;
    }

    // ---- prologue: A tile (swizzled) + first two B chunks ----
    {
        const __half* srcA = g_f1h + ((size_t)b * kM + (size_t)mtile * 128) * kC;
        #pragma unroll
        for (int j = 0; j < 16; j++) {
            int i = tid + j * 256;      // 4096 x 16B
            int r = i >> 5, seg = i & 31;
            cp16(sAu + r * 512 + ((seg ^ (r & 7)) << 4), srcA + (size_t)r * kC + seg * 8);
        }
        issueB(sBu[0], tid, b, (ngrp * kNSUB) * 128, 0);
        cp_commit();                    // group: A + chunk0
        issueB(sBu[1], tid, b, (ngrp * kNSUB) * 128, 1);
        cp_commit();                    // group: chunk1
    }

    float acc[4][4][4];
    #pragma unroll
    for (int mf = 0; mf < 4; mf++)
        #pragma unroll
        for (int nf = 0; nf < 4; nf++)
            #pragma unroll
            for (int i = 0; i < 4; i++) acc[mf][nf][i] = 0.0f;

    int bufsel = 0;                     // j % 3
    for (int j = 0; j < nchunks; j++) {
        if (j == nchunks - 1) cp_wait0(); else cp_wait1();
        __syncthreads();

        // prefetch chunk j+2 into buffer (j+2)%3 (last read at chunk j-1)
        if (j + 2 < nchunks) {
            int jn = j + 2;
            int bn = bufsel + 2; if (bn >= 3) bn -= 3;
            issueB(sBu[bn], tid, b, (ngrp * kNSUB + (jn >> 2)) * 128, jn & 3);
            cp_commit();
        }

        uint32_t sBc = sBu[bufsel];
        int kc = j & 3;

        #pragma unroll
        for (int ks = 0; ks < 4; ks++) {
            int uA = kc * 8 + ks * 2 + ulane;
            int uB = ks * 2 + ulane;
            uint32_t af[4][4], bq[2][4];
            #pragma unroll
            for (int mf = 0; mf < 4; mf++)
                ldm_x4(af[mf], aRow[mf] + ((uA ^ aX[mf]) << 4));
            #pragma unroll
            for (int np = 0; np < 2; np++)
                ldm_x4(bq[np], sBc + bRow[np] + ((uB ^ bX[np]) << 4));
            #pragma unroll
            for (int mf = 0; mf < 4; mf++)
                #pragma unroll
                for (int nf = 0; nf < 4; nf++) {
                    uint32_t bfr[2] = {bq[nf >> 1][nf & 1], bq[nf >> 1][2 + (nf & 1)]};
                    mma16816(acc[mf][nf], af[mf], bfr);
                }
        }

        if ((j & 3) == 3) {
            // epilogue for subtile s = j>>2, fp16 stores (register-only inputs)
            int s = j >> 2;
            int pbase = (ngrp * kNSUB + s) * 128 + wn * 32;
            #pragma unroll
            for (int mf = 0; mf < 4; mf++) {
                int m0 = mtile * 128 + wm * 64 + mf * 16 + g;
                __half* row0 = g_corr + ((size_t)b * kM + m0) * kPPad + pbase;
                __half* row1 = row0 + 8 * kPPad;
                #pragma unroll
                for (int nf = 0; nf < 4; nf++) {
                    __half2 v01 = __floats2half2_rn(acc[mf][nf][0], acc[mf][nf][1]);
                    __half2 v23 = __floats2half2_rn(acc[mf][nf][2], acc[mf][nf][3]);
                    *reinterpret_cast<__half2*>(row0 + nf * 8 + t2) = v01;
                    *reinterpret_cast<__half2*>(row1 + nf * 8 + t2) = v23;
                    acc[mf][nf][0] = 0.0f; acc[mf][nf][1] = 0.0f;
                    acc[mf][nf][2] = 0.0f; acc[mf][nf][3] = 0.0f;
                }
            }
        }

        if (++bufsel == 3) bufsel = 0;
    }
}

// ---------------------------------------------------------------------------
// Kernel 4: sample taps from fp16 corr. Block = 32 queries x 128 threads.
// Coalesced 128B output stores.
// ---------------------------------------------------------------------------
__global__ void __launch_bounds__(128) k_sample(const float* __restrict__ coords,
                                                float* __restrict__ out) {
    __shared__ float Dsh[32][101];
    __shared__ float cxs[32], cys[32];

    int qt = blockIdx.x;
    int b  = qt >> 7;
    int m0 = (qt & 127) * 32;
    int tid = threadIdx.x;
    int qlocal = tid & 31;
    int sub    = tid >> 5;

    if (tid < 32) {
        int q = b * kM + m0 + tid;
        cxs[tid] = coords[(size_t)q * 2 + 0];
        cys[tid] = coords[(size_t)q * 2 + 1];
    }
    __syncthreads();

    float clx = cxs[qlocal];
    float cly = cys[qlocal];
    const __half* crow = g_corr + (size_t)(b * kM + m0 + qlocal) * kPPad;

    for (int l = 0; l < kLevels; l++) {
        int Wl = kW >> l, Hl = kH >> l;
        float fx0 = floorf(clx), fy0 = floorf(cly);
        int ix0 = (int)fx0 - kRad;
        int iy0 = (int)fy0 - kRad;
        float wx1 = clx - fx0, wx0 = 1.0f - wx1;
        float wy1 = cly - fy0, wy0 = 1.0f - wy1;

        #pragma unroll 5
        for (int i = 0; i < 25; i++) {
            int p = sub * 25 + i;
            int py = p / 10, px = p - py * 10;
            int txp = ix0 + px, typ = iy0 + py;
            float v = 0.0f;
            if ((unsigned)txp < (unsigned)Wl && (unsigned)typ < (unsigned)Hl)
                v = __half2float(crow[c_lvl_off[l] + typ * Wl + txp]);
            Dsh[qlocal][p] = v;
        }
        __syncthreads();

        #pragma unroll
        for (int it = 0; it < 21; it++) {
            int f = it * 4 + sub;
            if (f < 81) {
                int ixo = f / 9;
                int iyo = f - ixo * 9;
                float d00 = Dsh[qlocal][iyo * 10 + ixo];
                float d01 = Dsh[qlocal][iyo * 10 + ixo + 1];
                float d10 = Dsh[qlocal][iyo * 10 + ixo + 10];
                float d11 = Dsh[qlocal][iyo * 10 + ixo + 11];
                float val = wy0 * (wx0 * d00 + wx1 * d01) + wy1 * (wx0 * d10 + wx1 * d11);
                out[((size_t)b * kFeat + l * 81 + f) * kM + m0 + qlocal] = val;
            }
        }
        __syncthreads();

        clx *= 0.5f;
        cly *= 0.5f;
    }
}

// ---------------------------------------------------------------------------
extern "C" void kernel_launch(void* const* d_in, const int* in_sizes, int n_in,
                              void* d_out, int out_size) {
    const float* fmap1  = (const float*)d_in[0];
    const float* fmap2  = (const float*)d_in[1];
    const float* coords = (const float*)d_in[2];
    float* out = (float*)d_out;

    k_prep<<<2048 + 512, dim3(32, 32)>>>(fmap2, (const float4*)fmap1);
    k_pool_fused<<<256, 256>>>();

    cudaFuncSetAttribute(k_gemm, cudaFuncAttributeMaxDynamicSharedMemorySize, kGemmSmem);
    k_gemm<<<dim3(kNGRP, kM / 128, kB), 256, kGemmSmem>>>();

    k_sample<<<256, 128>>>(coords, out);
}

// round 13
// speedup vs baseline: 1.6532x; 1.0462x over previous
#include <cuda_runtime.h>
#include <cuda_fp16.h>
#include <cstdint>

// ---------------------------------------------------------------------------
// Problem constants
// ---------------------------------------------------------------------------
constexpr int kB = 2;
constexpr int kM = 4096;
constexpr int kC = 256;
constexpr int kH = 64;
constexpr int kW = 64;
constexpr int kLevels = 4;
constexpr int kRad = 4;
constexpr int kSide = 9;
constexpr int kFeat = kLevels * kSide * kSide;          // 324
constexpr int kP    = 4096 + 1024 + 256 + 64;           // 5440 positions / batch
constexpr int kPPad = 5504;                             // 43 * 128
constexpr int kNT   = 43;                               // N tiles of 128
constexpr int kNSUB = 2;                                // N tiles per CTA
constexpr int kNGRP = 22;                               // ceil(43/2)

// Static device scratch (zero-initialized; g_pyrh pad rows stay zero)
__device__ float  g_pyrf[(size_t)kB * kPPad * kC];      // fp32 level-0 (pool source)
__device__ __half g_pyrh[(size_t)kB * kPPad * kC];      // fp16 GEMM B operand (all levels)
__device__ __half g_f1h [(size_t)kB * kM * kC];         // fp16 GEMM A operand
__device__ __half g_corr[(size_t)kB * kM * kPPad];      // fp16 correlation pyramid

__constant__ int c_lvl_off[4] = {0, 4096, 5120, 5376};

// ---------------------------------------------------------------------------
// Helpers (baseline PTX only — nothing 'a'-gated; ptxas targets sm_103)
// ---------------------------------------------------------------------------
__device__ __forceinline__ uint32_t smem_u32(const void* p) {
    uint32_t a;
    asm("{ .reg .u64 t; cvta.to.shared.u64 t, %1; cvt.u32.u64 %0, t; }" : "=r"(a) : "l"(p));
    return a;
}
__device__ __forceinline__ void cp16(uint32_t dst, const void* src) {
    asm volatile("cp.async.cg.shared.global [%0], [%1], 16;" :: "r"(dst), "l"(src));
}
__device__ __forceinline__ void cp_commit() { asm volatile("cp.async.commit_group;" ::: "memory"); }
__device__ __forceinline__ void cp_wait1()  { asm volatile("cp.async.wait_group 1;" ::: "memory"); }
__device__ __forceinline__ void cp_wait0()  { asm volatile("cp.async.wait_group 0;" ::: "memory"); }
__device__ __forceinline__ void mma16816(float* c, const uint32_t* a, const uint32_t* b) {
    asm volatile(
        "mma.sync.aligned.m16n8k16.row.col.f32.f16.f16.f32 "
        "{%0,%1,%2,%3}, {%4,%5,%6,%7}, {%8,%9}, {%0,%1,%2,%3};"
        : "+f"(c[0]), "+f"(c[1]), "+f"(c[2]), "+f"(c[3])
        : "r"(a[0]), "r"(a[1]), "r"(a[2]), "r"(a[3]), "r"(b[0]), "r"(b[1]));
}
__device__ __forceinline__ void ldm_x4(uint32_t* r, uint32_t addr) {
    asm volatile("ldmatrix.sync.aligned.m8n8.x4.shared.b16 {%0,%1,%2,%3}, [%4];"
                 : "=r"(r[0]), "=r"(r[1]), "=r"(r[2]), "=r"(r[3]) : "r"(addr));
}

// ---------------------------------------------------------------------------
// Kernel 1 (fused): transpose fmap2 (B,C,H,W) -> (B,pos,C) fp32+fp16 level 0,
// AND fmap1 fp32 -> fp16 (blocks >= 2048 do the convert).
// ---------------------------------------------------------------------------
__global__ void k_prep(const float* __restrict__ fmap2, const float4* __restrict__ f1) {
    if (blockIdx.x >= 2048) {
        int i = (blockIdx.x - 2048) * 1024 + threadIdx.y * 32 + threadIdx.x;
        float4 v = f1[i];
        __half2 a = __floats2half2_rn(v.x, v.y);
        __half2 b = __floats2half2_rn(v.z, v.w);
        uint2 u;
        u.x = *reinterpret_cast<uint32_t*>(&a);
        u.y = *reinterpret_cast<uint32_t*>(&b);
        reinterpret_cast<uint2*>(g_f1h)[i] = u;
        return;
    }
    __shared__ float s[32][33];
    int bidx = blockIdx.x;
    int ct = bidx & 7;  bidx >>= 3;
    int xt = bidx & 1;  bidx >>= 1;
    int y  = bidx & 63; bidx >>= 6;
    int b  = bidx;
    int tx = threadIdx.x, ty = threadIdx.y;
    s[ty][tx] = fmap2[(((size_t)b * kC + ct * 32 + ty) * kH + y) * kW + (xt * 32 + tx)];
    __syncthreads();
    float v = s[tx][ty];
    size_t o = ((size_t)b * kPPad + (size_t)y * kW + (xt * 32 + ty)) * kC + (ct * 32 + tx);
    g_pyrf[o] = v;
    g_pyrh[o] = __float2half(v);
}

// ---------------------------------------------------------------------------
// Kernel 2 (fused): build pyramid levels 1..3 in one launch.
// ---------------------------------------------------------------------------
__global__ void __launch_bounds__(256) k_pool_fused() {
    __shared__ float s0[256][33];
    __shared__ float s1[64][33];
    __shared__ float s2[16][33];

    int bidx = blockIdx.x;
    int cc = bidx & 7;  bidx >>= 3;
    int xt = bidx & 3;  bidx >>= 2;
    int yt = bidx & 3;  bidx >>= 2;
    int b  = bidx;
    int tid = threadIdx.x;

    const float* src = g_pyrf + ((size_t)b * kPPad) * kC + cc * 32;
    #pragma unroll
    for (int j = 0; j < 8; j++) {
        int idx = tid + j * 256;
        int pos = idx >> 3, cseg = idx & 7;
        int py = pos >> 4, px = pos & 15;
        const float4 v = *reinterpret_cast<const float4*>(
            src + ((size_t)(yt * 16 + py) * kW + (xt * 16 + px)) * kC + cseg * 4);
        s0[pos][cseg * 4 + 0] = v.x;
        s0[pos][cseg * 4 + 1] = v.y;
        s0[pos][cseg * 4 + 2] = v.z;
        s0[pos][cseg * 4 + 3] = v.w;
    }
    __syncthreads();

    {
        int pos1 = tid >> 2;
        int c0 = (tid & 3) * 8;
        int y1 = pos1 >> 3, x1 = pos1 & 7;
        int pa = (2 * y1) * 16 + 2 * x1;
        __half h[8];
        #pragma unroll
        for (int c = 0; c < 8; c++) {
            float v = 0.25f * (s0[pa][c0 + c] + s0[pa + 1][c0 + c] +
                               s0[pa + 16][c0 + c] + s0[pa + 17][c0 + c]);
            s1[pos1][c0 + c] = v;
            h[c] = __float2half(v);
        }
        size_t o = ((size_t)b * kPPad + 4096 + (size_t)(yt * 8 + y1) * 32 + (xt * 8 + x1)) * kC
                 + cc * 32 + c0;
        *reinterpret_cast<uint4*>(g_pyrh + o) = *reinterpret_cast<uint4*>(h);
    }
    __syncthreads();

    if (tid < 128) {
        int pos2 = tid >> 3;
        int c0 = (tid & 7) * 4;
        int y2 = pos2 >> 2, x2 = pos2 & 3;
        int pa = (2 * y2) * 8 + 2 * x2;
        __half h[4];
        #pragma unroll
        for (int c = 0; c < 4; c++) {
            float v = 0.25f * (s1[pa][c0 + c] + s1[pa + 1][c0 + c] +
                               s1[pa + 8][c0 + c] + s1[pa + 9][c0 + c]);
            s2[pos2][c0 + c] = v;
            h[c] = __float2half(v);
        }
        size_t o = ((size_t)b * kPPad + 5120 + (size_t)(yt * 4 + y2) * 16 + (xt * 4 + x2)) * kC
                 + cc * 32 + c0;
        *reinterpret_cast<uint2*>(g_pyrh + o) = *reinterpret_cast<uint2*>(h);
    }
    __syncthreads();

    if (tid < 128) {
        int pos3 = tid >> 5;
        int c = tid & 31;
        int y3 = pos3 >> 1, x3 = pos3 & 1;
        int pa = (2 * y3) * 4 + 2 * x3;
        float v = 0.25f * (s2[pa][c] + s2[pa + 1][c] + s2[pa + 4][c] + s2[pa + 5][c]);
        size_t o = ((size_t)b * kPPad + 5376 + (size_t)(yt * 2 + y3) * 8 + (xt * 2 + x3)) * kC
                 + cc * 32 + c;
        g_pyrh[o] = __float2half(v);
    }
}

// ---------------------------------------------------------------------------
// Kernel 3: HMMA GEMM  corr[b, m, p] = sum_c f1h[b,m,c] * pyrh[b,p,c]
// A tile 128x256 resident (XOR-swizzled, 64KB). B: 3-stage ring of 16KB
// chunks, one barrier per chunk, prefetch distance 2. 2 CTAs/SM.
// ---------------------------------------------------------------------------
constexpr int kABytes = 128 * 512;                      // 65536, swizzled
constexpr int kBChunkBytes = 128 * 128;                 // 16384, swizzled
constexpr int kGemmSmem = kABytes + 3 * kBChunkBytes;   // 114688

__device__ __forceinline__ void issueB(uint32_t sB, int tid, int b, int pbase, int kc) {
    const __half* src0 = g_pyrh + ((size_t)b * kPPad + pbase) * kC + kc * 64;
    #pragma unroll
    for (int j = 0; j < 4; j++) {
        int i = tid + j * 256;          // 1024 x 16B
        int n = i >> 3, seg = i & 7;
        cp16(sB + n * 128 + ((seg ^ (n & 7)) << 4), src0 + (size_t)n * kC + seg * 8);
    }
}

__global__ void __launch_bounds__(256, 2) k_gemm() {
    extern __shared__ char smem[];
    uint32_t sAu = smem_u32(smem);
    uint32_t sBu[3] = {sAu + kABytes, sAu + kABytes + kBChunkBytes,
                       sAu + kABytes + 2 * kBChunkBytes};

    int tid  = threadIdx.x;
    int wid  = tid >> 5, lane = tid & 31;
    int g    = lane >> 2;
    int t2   = (lane & 3) * 2;
    int wm   = wid & 1;                 // 2 warps along M
    int wn   = wid >> 1;                // 4 warps along N

    int ngrp  = blockIdx.x;             // 0..21
    int mtile = blockIdx.y;             // 0..31
    int b     = blockIdx.z;             // 0..1
    int ns = min(kNSUB, kNT - ngrp * kNSUB);
    int nchunks = ns * 4;

    int lrow  = (lane & 7) + ((lane >> 3) & 1) * 8;
    int ulane = (lane >> 4) & 1;

    uint32_t aRow[4]; int aX[4];
    #pragma unroll
    for (int mf = 0; mf < 4; mf++) {
        int r = wm * 64 + mf * 16 + lrow;
        aRow[mf] = sAu + r * 512;
        aX[mf] = r & 7;
    }
    uint32_t bRow[2]; int bX[2];
    #pragma unroll
    for (int np = 0; np < 2; np++) {
        int n = wn * 32 + np * 16 + lrow;
        bRow[np] = n * 128;
        bX[np] = n & 7;
    }

    // epilogue base (row for g lane, column base wn*32)
    __half* epiBase = g_corr + ((size_t)b * kM + mtile * 128 + wm * 64 + g) * kPPad
                    + ngrp * kNSUB * 128 + wn * 32 + t2;

    // ---- prologue ----
    {
        const __half* srcA = g_f1h + ((size_t)b * kM + (size_t)mtile * 128) * kC;
        #pragma unroll
        for (int j = 0; j < 16; j++) {
            int i = tid + j * 256;
            int r = i >> 5, seg = i & 31;
            cp16(sAu + r * 512 + ((seg ^ (r & 7)) << 4), srcA + (size_t)r * kC + seg * 8);
        }
        issueB(sBu[0], tid, b, (ngrp * kNSUB) * 128, 0);
        cp_commit();
        issueB(sBu[1], tid, b, (ngrp * kNSUB) * 128, 1);
        cp_commit();
    }

    float acc[4][4][4];
    #pragma unroll
    for (int mf = 0; mf < 4; mf++)
        #pragma unroll
        for (int nf = 0; nf < 4; nf++)
            #pragma unroll
            for (int i = 0; i < 4; i++) acc[mf][nf][i] = 0.0f;

    int bufsel = 0;
    for (int j = 0; j < nchunks; j++) {
        if (j == nchunks - 1) cp_wait0(); else cp_wait1();
        __syncthreads();

        if (j + 2 < nchunks) {
            int jn = j + 2;
            int bn = bufsel + 2; if (bn >= 3) bn -= 3;
            issueB(sBu[bn], tid, b, (ngrp * kNSUB + (jn >> 2)) * 128, jn & 3);
            cp_commit();
        }

        uint32_t sBc = sBu[bufsel];
        int kc = j & 3;

        #pragma unroll
        for (int ks = 0; ks < 4; ks++) {
            int uA = kc * 8 + ks * 2 + ulane;
            int uB = ks * 2 + ulane;
            uint32_t af[4][4], bq[2][4];
            #pragma unroll
            for (int mf = 0; mf < 4; mf++)
                ldm_x4(af[mf], aRow[mf] + ((uA ^ aX[mf]) << 4));
            #pragma unroll
            for (int np = 0; np < 2; np++)
                ldm_x4(bq[np], sBc + bRow[np] + ((uB ^ bX[np]) << 4));
            #pragma unroll
            for (int mf = 0; mf < 4; mf++)
                #pragma unroll
                for (int nf = 0; nf < 4; nf++) {
                    uint32_t bfr[2] = {bq[nf >> 1][nf & 1], bq[nf >> 1][2 + (nf & 1)]};
                    mma16816(acc[mf][nf], af[mf], bfr);
                }
        }

        if ((j & 3) == 3) {
            int s = j >> 2;
            #pragma unroll
            for (int mf = 0; mf < 4; mf++) {
                __half* row0 = epiBase + (size_t)(mf * 16) * kPPad + s * 128;
                __half* row1 = row0 + 8 * kPPad;
                #pragma unroll
                for (int nf = 0; nf < 4; nf++) {
                    __half2 v01 = __floats2half2_rn(acc[mf][nf][0], acc[mf][nf][1]);
                    __half2 v23 = __floats2half2_rn(acc[mf][nf][2], acc[mf][nf][3]);
                    *reinterpret_cast<__half2*>(row0 + nf * 8) = v01;
                    *reinterpret_cast<__half2*>(row1 + nf * 8) = v23;
                    acc[mf][nf][0] = 0.0f; acc[mf][nf][1] = 0.0f;
                    acc[mf][nf][2] = 0.0f; acc[mf][nf][3] = 0.0f;
                }
            }
        }

        if (++bufsel == 3) bufsel = 0;
    }
}

// ---------------------------------------------------------------------------
// Kernel 4: sample taps from fp16 corr. Block = (32 queries, ONE level),
// grid = (256 qtiles, 4 levels). Coalesced 128B output stores.
// ---------------------------------------------------------------------------
__global__ void __launch_bounds__(128) k_sample(const float* __restrict__ coords,
                                                float* __restrict__ out) {
    __shared__ float Dsh[32][101];
    __shared__ float cxs[32], cys[32];

    int qt = blockIdx.x;                // 0..255
    int l  = blockIdx.y;                // 0..3
    int b  = qt >> 7;
    int m0 = (qt & 127) * 32;
    int tid = threadIdx.x;
    int qlocal = tid & 31;
    int sub    = tid >> 5;

    if (tid < 32) {
        int q = b * kM + m0 + tid;
        cxs[tid] = coords[(size_t)q * 2 + 0];
        cys[tid] = coords[(size_t)q * 2 + 1];
    }
    __syncthreads();

    float scale = 1.0f / (float)(1 << l);
    float clx = cxs[qlocal] * scale;
    float cly = cys[qlocal] * scale;
    const __half* crow = g_corr + (size_t)(b * kM + m0 + qlocal) * kPPad + c_lvl_off[l];

    int Wl = kW >> l, Hl = kH >> l;
    float fx0 = floorf(clx), fy0 = floorf(cly);
    int ix0 = (int)fx0 - kRad;
    int iy0 = (int)fy0 - kRad;
    float wx1 = clx - fx0, wx0 = 1.0f - wx1;
    float wy1 = cly - fy0, wy0 = 1.0f - wy1;

    #pragma unroll 5
    for (int i = 0; i < 25; i++) {
        int p = sub * 25 + i;
        int py = p / 10, px = p - py * 10;
        int txp = ix0 + px, typ = iy0 + py;
        float v = 0.0f;
        if ((unsigned)txp < (unsigned)Wl && (unsigned)typ < (unsigned)Hl)
            v = __half2float(__ldg(crow + typ * Wl + txp));
        Dsh[qlocal][p] = v;
    }
    __syncthreads();

    float* obase = out + ((size_t)b * kFeat + l * 81) * kM + m0 + qlocal;
    #pragma unroll
    for (int it = 0; it < 21; it++) {
        int f = it * 4 + sub;
        if (f < 81) {
            int ixo = f / 9;
            int iyo = f - ixo * 9;
            float d00 = Dsh[qlocal][iyo * 10 + ixo];
            float d01 = Dsh[qlocal][iyo * 10 + ixo + 1];
            float d10 = Dsh[qlocal][iyo * 10 + ixo + 10];
            float d11 = Dsh[qlocal][iyo * 10 + ixo + 11];
            float val = wy0 * (wx0 * d00 + wx1 * d01) + wy1 * (wx0 * d10 + wx1 * d11);
            obase[(size_t)f * kM] = val;
        }
    }
}

// ---------------------------------------------------------------------------
extern "C" void kernel_launch(void* const* d_in, const int* in_sizes, int n_in,
                              void* d_out, int out_size) {
    const float* fmap1  = (const float*)d_in[0];
    const float* fmap2  = (const float*)d_in[1];
    const float* coords = (const float*)d_in[2];
    float* out = (float*)d_out;

    k_prep<<<2048 + 512, dim3(32, 32)>>>(fmap2, (const float4*)fmap1);
    k_pool_fused<<<256, 256>>>();

    cudaFuncSetAttribute(k_gemm, cudaFuncAttributeMaxDynamicSharedMemorySize, kGemmSmem);
    k_gemm<<<dim3(kNGRP, kM / 128, kB), 256, kGemmSmem>>>();

    k_sample<<<dim3(256, 4), 128>>>(coords, out);
}

// round 14
// speedup vs baseline: 1.7957x; 1.0862x over previous
#include <cuda_runtime.h>
#include <cuda_fp16.h>
#include <cstdint>

// ---------------------------------------------------------------------------
// Problem constants
// ---------------------------------------------------------------------------
constexpr int kB = 2;
constexpr int kM = 4096;
constexpr int kC = 256;
constexpr int kH = 64;
constexpr int kW = 64;
constexpr int kLevels = 4;
constexpr int kRad = 4;
constexpr int kSide = 9;
constexpr int kFeat = kLevels * kSide * kSide;          // 324
constexpr int kP    = 4096 + 1024 + 256 + 64;           // 5440 positions / batch
constexpr int kPPad = 5504;                             // 43 * 128
constexpr int kNT   = 43;                               // N tiles of 128
constexpr int kNSUB = 2;                                // N tiles per CTA
constexpr int kNGRP = 22;                               // ceil(43/2)

// Static device scratch (zero-initialized; g_pyrh pad rows stay zero)
__device__ __half g_pyrh[(size_t)kB * kPPad * kC];      // fp16 GEMM B operand (all levels)
__device__ __half g_f1h [(size_t)kB * kM * kC];         // fp16 GEMM A operand
__device__ __half g_corr[(size_t)kB * kM * kPPad];      // fp16 correlation pyramid

__constant__ int c_lvl_off[4] = {0, 4096, 5120, 5376};

// ---------------------------------------------------------------------------
// Helpers (baseline PTX only — nothing 'a'-gated; ptxas targets sm_103)
// ---------------------------------------------------------------------------
__device__ __forceinline__ uint32_t smem_u32(const void* p) {
    uint32_t a;
    asm("{ .reg .u64 t; cvta.to.shared.u64 t, %1; cvt.u32.u64 %0, t; }" : "=r"(a) : "l"(p));
    return a;
}
__device__ __forceinline__ void cp16(uint32_t dst, const void* src) {
    asm volatile("cp.async.cg.shared.global [%0], [%1], 16;" :: "r"(dst), "l"(src));
}
__device__ __forceinline__ void cp_commit() { asm volatile("cp.async.commit_group;" ::: "memory"); }
__device__ __forceinline__ void cp_wait1()  { asm volatile("cp.async.wait_group 1;" ::: "memory"); }
__device__ __forceinline__ void cp_wait0()  { asm volatile("cp.async.wait_group 0;" ::: "memory"); }
__device__ __forceinline__ void mma16816(float* c, const uint32_t* a, const uint32_t* b) {
    asm volatile(
        "mma.sync.aligned.m16n8k16.row.col.f32.f16.f16.f32 "
        "{%0,%1,%2,%3}, {%4,%5,%6,%7}, {%8,%9}, {%0,%1,%2,%3};"
        : "+f"(c[0]), "+f"(c[1]), "+f"(c[2]), "+f"(c[3])
        : "r"(a[0]), "r"(a[1]), "r"(a[2]), "r"(a[3]), "r"(b[0]), "r"(b[1]));
}
__device__ __forceinline__ void ldm_x4(uint32_t* r, uint32_t addr) {
    asm volatile("ldmatrix.sync.aligned.m8n8.x4.shared.b16 {%0,%1,%2,%3}, [%4];"
                 : "=r"(r[0]), "=r"(r[1]), "=r"(r[2]), "=r"(r[3]) : "r"(addr));
}

// ---------------------------------------------------------------------------
// Kernel 1 (fused): transpose fmap2 (B,C,H,W) -> (B,pos,C) fp16 level 0,
// AND fmap1 fp32 -> fp16 (blocks >= 2048 do the convert).
// ---------------------------------------------------------------------------
__global__ void k_prep(const float* __restrict__ fmap2, const float4* __restrict__ f1) {
    if (blockIdx.x >= 2048) {
        int i = (blockIdx.x - 2048) * 1024 + threadIdx.y * 32 + threadIdx.x;
        float4 v = f1[i];
        __half2 a = __floats2half2_rn(v.x, v.y);
        __half2 b = __floats2half2_rn(v.z, v.w);
        uint2 u;
        u.x = *reinterpret_cast<uint32_t*>(&a);
        u.y = *reinterpret_cast<uint32_t*>(&b);
        reinterpret_cast<uint2*>(g_f1h)[i] = u;
        return;
    }
    __shared__ float s[32][33];
    int bidx = blockIdx.x;
    int ct = bidx & 7;  bidx >>= 3;
    int xt = bidx & 1;  bidx >>= 1;
    int y  = bidx & 63; bidx >>= 6;
    int b  = bidx;
    int tx = threadIdx.x, ty = threadIdx.y;
    s[ty][tx] = fmap2[(((size_t)b * kC + ct * 32 + ty) * kH + y) * kW + (xt * 32 + tx)];
    __syncthreads();
    float v = s[tx][ty];
    size_t o = ((size_t)b * kPPad + (size_t)y * kW + (xt * 32 + ty)) * kC + (ct * 32 + tx);
    g_pyrh[o] = __float2half(v);
}

// ---------------------------------------------------------------------------
// Kernel 2 (fused): build pyramid levels 1..3 in one launch, sourcing the
// fp16 level-0 (fp32 arithmetic in smem).
// ---------------------------------------------------------------------------
__global__ void __launch_bounds__(256) k_pool_fused() {
    __shared__ float s0[256][33];
    __shared__ float s1[64][33];
    __shared__ float s2[16][33];

    int bidx = blockIdx.x;
    int cc = bidx & 7;  bidx >>= 3;
    int xt = bidx & 3;  bidx >>= 2;
    int yt = bidx & 3;  bidx >>= 2;
    int b  = bidx;
    int tid = threadIdx.x;

    const __half* src = g_pyrh + ((size_t)b * kPPad) * kC + cc * 32;
    #pragma unroll
    for (int j = 0; j < 4; j++) {
        int idx = tid + j * 256;        // 1024 uint4 (8 halves each)
        int pos = idx >> 2, cseg = idx & 3;
        int py = pos >> 4, px = pos & 15;
        uint4 u = *reinterpret_cast<const uint4*>(
            src + ((size_t)(yt * 16 + py) * kW + (xt * 16 + px)) * kC + cseg * 8);
        const __half2* h2 = reinterpret_cast<const __half2*>(&u);
        #pragma unroll
        for (int k2 = 0; k2 < 4; k2++) {
            float2 f = __half22float2(h2[k2]);
            s0[pos][cseg * 8 + k2 * 2 + 0] = f.x;
            s0[pos][cseg * 8 + k2 * 2 + 1] = f.y;
        }
    }
    __syncthreads();

    {
        int pos1 = tid >> 2;
        int c0 = (tid & 3) * 8;
        int y1 = pos1 >> 3, x1 = pos1 & 7;
        int pa = (2 * y1) * 16 + 2 * x1;
        __half h[8];
        #pragma unroll
        for (int c = 0; c < 8; c++) {
            float v = 0.25f * (s0[pa][c0 + c] + s0[pa + 1][c0 + c] +
                               s0[pa + 16][c0 + c] + s0[pa + 17][c0 + c]);
            s1[pos1][c0 + c] = v;
            h[c] = __float2half(v);
        }
        size_t o = ((size_t)b * kPPad + 4096 + (size_t)(yt * 8 + y1) * 32 + (xt * 8 + x1)) * kC
                 + cc * 32 + c0;
        *reinterpret_cast<uint4*>(g_pyrh + o) = *reinterpret_cast<uint4*>(h);
    }
    __syncthreads();

    if (tid < 128) {
        int pos2 = tid >> 3;
        int c0 = (tid & 7) * 4;
        int y2 = pos2 >> 2, x2 = pos2 & 3;
        int pa = (2 * y2) * 8 + 2 * x2;
        __half h[4];
        #pragma unroll
        for (int c = 0; c < 4; c++) {
            float v = 0.25f * (s1[pa][c0 + c] + s1[pa + 1][c0 + c] +
                               s1[pa + 8][c0 + c] + s1[pa + 9][c0 + c]);
            s2[pos2][c0 + c] = v;
            h[c] = __float2half(v);
        }
        size_t o = ((size_t)b * kPPad + 5120 + (size_t)(yt * 4 + y2) * 16 + (xt * 4 + x2)) * kC
                 + cc * 32 + c0;
        *reinterpret_cast<uint2*>(g_pyrh + o) = *reinterpret_cast<uint2*>(h);
    }
    __syncthreads();

    if (tid < 128) {
        int pos3 = tid >> 5;
        int c = tid & 31;
        int y3 = pos3 >> 1, x3 = pos3 & 1;
        int pa = (2 * y3) * 4 + 2 * x3;
        float v = 0.25f * (s2[pa][c] + s2[pa + 1][c] + s2[pa + 4][c] + s2[pa + 5][c]);
        size_t o = ((size_t)b * kPPad + 5376 + (size_t)(yt * 2 + y3) * 8 + (xt * 2 + x3)) * kC
                 + cc * 32 + c;
        g_pyrh[o] = __float2half(v);
    }
}

// ---------------------------------------------------------------------------
// Kernel 3: HMMA GEMM (unchanged from round 12/13 — isolate sampler change)
// ---------------------------------------------------------------------------
constexpr int kABytes = 128 * 512;                      // 65536, swizzled
constexpr int kBChunkBytes = 128 * 128;                 // 16384, swizzled
constexpr int kGemmSmem = kABytes + 3 * kBChunkBytes;   // 114688

__device__ __forceinline__ void issueB(uint32_t sB, int tid, int b, int pbase, int kc) {
    const __half* src0 = g_pyrh + ((size_t)b * kPPad + pbase) * kC + kc * 64;
    #pragma unroll
    for (int j = 0; j < 4; j++) {
        int i = tid + j * 256;          // 1024 x 16B
        int n = i >> 3, seg = i & 7;
        cp16(sB + n * 128 + ((seg ^ (n & 7)) << 4), src0 + (size_t)n * kC + seg * 8);
    }
}

__global__ void __launch_bounds__(256, 2) k_gemm() {
    extern __shared__ char smem[];
    uint32_t sAu = smem_u32(smem);
    uint32_t sBu[3] = {sAu + kABytes, sAu + kABytes + kBChunkBytes,
                       sAu + kABytes + 2 * kBChunkBytes};

    int tid  = threadIdx.x;
    int wid  = tid >> 5, lane = tid & 31;
    int g    = lane >> 2;
    int t2   = (lane & 3) * 2;
    int wm   = wid & 1;
    int wn   = wid >> 1;

    int ngrp  = blockIdx.x;
    int mtile = blockIdx.y;
    int b     = blockIdx.z;
    int ns = min(kNSUB, kNT - ngrp * kNSUB);
    int nchunks = ns * 4;

    int lrow  = (lane & 7) + ((lane >> 3) & 1) * 8;
    int ulane = (lane >> 4) & 1;

    uint32_t aRow[4]; int aX[4];
    #pragma unroll
    for (int mf = 0; mf < 4; mf++) {
        int r = wm * 64 + mf * 16 + lrow;
        aRow[mf] = sAu + r * 512;
        aX[mf] = r & 7;
    }
    uint32_t bRow[2]; int bX[2];
    #pragma unroll
    for (int np = 0; np < 2; np++) {
        int n = wn * 32 + np * 16 + lrow;
        bRow[np] = n * 128;
        bX[np] = n & 7;
    }

    __half* epiBase = g_corr + ((size_t)b * kM + mtile * 128 + wm * 64 + g) * kPPad
                    + ngrp * kNSUB * 128 + wn * 32 + t2;

    {
        const __half* srcA = g_f1h + ((size_t)b * kM + (size_t)mtile * 128) * kC;
        #pragma unroll
        for (int j = 0; j < 16; j++) {
            int i = tid + j * 256;
            int r = i >> 5, seg = i & 31;
            cp16(sAu + r * 512 + ((seg ^ (r & 7)) << 4), srcA + (size_t)r * kC + seg * 8);
        }
        issueB(sBu[0], tid, b, (ngrp * kNSUB) * 128, 0);
        cp_commit();
        issueB(sBu[1], tid, b, (ngrp * kNSUB) * 128, 1);
        cp_commit();
    }

    float acc[4][4][4];
    #pragma unroll
    for (int mf = 0; mf < 4; mf++)
        #pragma unroll
        for (int nf = 0; nf < 4; nf++)
            #pragma unroll
            for (int i = 0; i < 4; i++) acc[mf][nf][i] = 0.0f;

    int bufsel = 0;
    for (int j = 0; j < nchunks; j++) {
        if (j == nchunks - 1) cp_wait0(); else cp_wait1();
        __syncthreads();

        if (j + 2 < nchunks) {
            int jn = j + 2;
            int bn = bufsel + 2; if (bn >= 3) bn -= 3;
            issueB(sBu[bn], tid, b, (ngrp * kNSUB + (jn >> 2)) * 128, jn & 3);
            cp_commit();
        }

        uint32_t sBc = sBu[bufsel];
        int kc = j & 3;

        #pragma unroll
        for (int ks = 0; ks < 4; ks++) {
            int uA = kc * 8 + ks * 2 + ulane;
            int uB = ks * 2 + ulane;
            uint32_t af[4][4], bq[2][4];
            #pragma unroll
            for (int mf = 0; mf < 4; mf++)
                ldm_x4(af[mf], aRow[mf] + ((uA ^ aX[mf]) << 4));
            #pragma unroll
            for (int np = 0; np < 2; np++)
                ldm_x4(bq[np], sBc + bRow[np] + ((uB ^ bX[np]) << 4));
            #pragma unroll
            for (int mf = 0; mf < 4; mf++)
                #pragma unroll
                for (int nf = 0; nf < 4; nf++) {
                    uint32_t bfr[2] = {bq[nf >> 1][nf & 1], bq[nf >> 1][2 + (nf & 1)]};
                    mma16816(acc[mf][nf], af[mf], bfr);
                }
        }

        if ((j & 3) == 3) {
            int s = j >> 2;
            #pragma unroll
            for (int mf = 0; mf < 4; mf++) {
                __half* row0 = epiBase + (size_t)(mf * 16) * kPPad + s * 128;
                __half* row1 = row0 + 8 * kPPad;
                #pragma unroll
                for (int nf = 0; nf < 4; nf++) {
                    __half2 v01 = __floats2half2_rn(acc[mf][nf][0], acc[mf][nf][1]);
                    __half2 v23 = __floats2half2_rn(acc[mf][nf][2], acc[mf][nf][3]);
                    *reinterpret_cast<__half2*>(row0 + nf * 8) = v01;
                    *reinterpret_cast<__half2*>(row1 + nf * 8) = v23;
                    acc[mf][nf][0] = 0.0f; acc[mf][nf][1] = 0.0f;
                    acc[mf][nf][2] = 0.0f; acc[mf][nf][3] = 0.0f;
                }
            }
        }

        if (++bufsel == 3) bufsel = 0;
    }
}

// ---------------------------------------------------------------------------
// Kernel 4: sampler. Block = (32 queries, ONE level). Tap loads are
// warp-per-query: lanes walk one query's 10x10 window (contiguous rows ->
// ~5 sectors per LDG instead of 32). OOB taps load a clamped in-row address
// and mask the value. Combine phase + coalesced stores unchanged.
// ---------------------------------------------------------------------------
__global__ void __launch_bounds__(128) k_sample(const float* __restrict__ coords,
                                                float* __restrict__ out) {
    __shared__ float Dsh[32][101];
    __shared__ float cxs[32], cys[32];

    int qt = blockIdx.x;                // 0..255
    int l  = blockIdx.y;                // 0..3
    int b  = qt >> 7;
    int m0 = (qt & 127) * 32;
    int tid = threadIdx.x;
    int lane = tid & 31;
    int w    = tid >> 5;                // 0..3

    if (tid < 32) {
        int q = b * kM + m0 + tid;
        cxs[tid] = coords[(size_t)q * 2 + 0];
        cys[tid] = coords[(size_t)q * 2 + 1];
    }
    __syncthreads();

    float scale = 1.0f / (float)(1 << l);
    int Wl = kW >> l, Hl = kH >> l;
    int loff = c_lvl_off[l];

    // tap phase: warp w loads queries w*8 .. w*8+7
    int py_l = -1, px_l = -1;
    {
        // precompute this lane's tap coords for each round (p = r*32 + lane)
        #pragma unroll
        for (int i = 0; i < 8; i++) {
            int qi = w * 8 + i;
            float qx = cxs[qi] * scale;
            float qy = cys[qi] * scale;
            int ix0 = (int)floorf(qx) - kRad;
            int iy0 = (int)floorf(qy) - kRad;
            const __half* crow = g_corr + (size_t)(b * kM + m0 + qi) * kPPad + loff;
            #pragma unroll
            for (int r = 0; r < 4; r++) {
                int p = r * 32 + lane;
                if (p < 100) {
                    py_l = p / 10; px_l = p - py_l * 10;
                    int txp = ix0 + px_l, typ = iy0 + py_l;
                    bool valid = ((unsigned)txp < (unsigned)Wl) & ((unsigned)typ < (unsigned)Hl);
                    int off = typ * Wl + txp;
                    off = off < 0 ? 0 : off;     // clamped address, value masked
                    float v = valid ? __half2float(__ldg(crow + off)) : 0.0f;
                    Dsh[qi][p] = v;
                }
            }
        }
    }
    __syncthreads();

    // combine phase: thread (qlocal=lane, sub=w) -> query lane, features f=it*4+w
    int qlocal = lane;
    float clx = cxs[qlocal] * scale;
    float cly = cys[qlocal] * scale;
    float fx0 = floorf(clx), fy0 = floorf(cly);
    float wx1 = clx - fx0, wx0 = 1.0f - wx1;
    float wy1 = cly - fy0, wy0 = 1.0f - wy1;

    float* obase = out + ((size_t)b * kFeat + l * 81) * kM + m0 + qlocal;
    #pragma unroll
    for (int it = 0; it < 21; it++) {
        int f = it * 4 + w;
        if (f < 81) {
            int ixo = f / 9;
            int iyo = f - ixo * 9;
            float d00 = Dsh[qlocal][iyo * 10 + ixo];
            float d01 = Dsh[qlocal][iyo * 10 + ixo + 1];
            float d10 = Dsh[qlocal][iyo * 10 + ixo + 10];
            float d11 = Dsh[qlocal][iyo * 10 + ixo + 11];
            float val = wy0 * (wx0 * d00 + wx1 * d01) + wy1 * (wx0 * d10 + wx1 * d11);
            obase[(size_t)f * kM] = val;
        }
    }
}

// ---------------------------------------------------------------------------
extern "C" void kernel_launch(void* const* d_in, const int* in_sizes, int n_in,
                              void* d_out, int out_size) {
    const float* fmap1  = (const float*)d_in[0];
    const float* fmap2  = (const float*)d_in[1];
    const float* coords = (const float*)d_in[2];
    float* out = (float*)d_out;

    k_prep<<<2048 + 512, dim3(32, 32)>>>(fmap2, (const float4*)fmap1);
    k_pool_fused<<<256, 256>>>();

    cudaFuncSetAttribute(k_gemm, cudaFuncAttributeMaxDynamicSharedMemorySize, kGemmSmem);
    k_gemm<<<dim3(kNGRP, kM / 128, kB), 256, kGemmSmem>>>();

    k_sample<<<dim3(256, 4), 128>>>(coords, out);
}